// round 2
// baseline (speedup 1.0000x reference)
#include <cuda_runtime.h>
#include <cstdint>

#define T_STEPS 1024
#define BATCH   512
#define DIM     128
#define GATES   384
#define RSU     65   // GEMM tile row stride in ull (130 floats, conflict-free)

typedef unsigned long long ull;

__device__ float g_Wc[GATES * DIM];
__device__ float g_bc[GATES];
__device__ float g_Wq[GATES * DIM];                      // [k4][col][4]
__device__ float g_GI[(size_t)T_STEPS * BATCH * GATES];  // 805 MB scratch

__device__ __forceinline__ void fma2(ull& acc, ull a, ull b) {
    asm("fma.rn.f32x2 %0, %1, %2, %0;" : "+l"(acc) : "l"(a), "l"(b));
}
__device__ __forceinline__ float sum2(ull v) {
    unsigned lo, hi;
    asm("mov.b64 {%0,%1}, %2;" : "=r"(lo), "=r"(hi) : "l"(v));
    return __uint_as_float(lo) + __uint_as_float(hi);
}
__device__ __forceinline__ float sigm(float x) {
    return __fdividef(1.f, 1.f + __expf(-x));
}

// ---------------- prep: fold fc1, repack W_hh ----------------
__global__ void prep_kernel(const float* __restrict__ W1, const float* __restrict__ b1,
                            const float* __restrict__ W_ih, const float* __restrict__ W_hh,
                            const float* __restrict__ b_ih) {
    int bid = blockIdx.x, tid = threadIdx.x;
    if (bid < GATES) {
        __shared__ float wih[DIM];
        __shared__ float red[DIM];
        wih[tid] = W_ih[bid * DIM + tid];
        __syncthreads();
        float acc = 0.f;
        #pragma unroll 8
        for (int k = 0; k < DIM; k++)
            acc = fmaf(wih[k], W1[k * DIM + tid], acc);
        g_Wc[bid * DIM + tid] = acc;
        red[tid] = wih[tid] * b1[tid];
        __syncthreads();
        if (tid == 0) {
            float s = 0.f;
            for (int k = 0; k < DIM; k++) s += red[k];
            g_bc[bid] = s + b_ih[bid];
        }
    } else {
        int col = bid - GATES;
        int k = tid;
        g_Wq[(k >> 2) * (GATES * 4) + col * 4 + (k & 3)] = W_hh[col * DIM + k];
    }
}

// ---------------- GI = X @ Wc^T + bc  (M=524288, N=384, K=128) ----------------
#define GSMEM (2 * 128 * 130 * 4)

__global__ __launch_bounds__(256, 1)
void gi_gemm_kernel(const float* __restrict__ X) {
    extern __shared__ float sm[];
    ull* Xu = (ull*)sm;                 // [128][65]
    ull* Wu = (ull*)(sm + 128 * 130);   // [128][65]

    const int m0 = blockIdx.x * 128;
    const int n0 = blockIdx.y * 128;
    const int tid = threadIdx.x;

    for (int s = tid; s < 128 * 32; s += 256) {
        int row = s >> 5, k4 = s & 31;
        float4 v = *(const float4*)(X + (size_t)(m0 + row) * DIM + k4 * 4);
        ulonglong2 u = *(ulonglong2*)&v;
        Xu[row * RSU + 2 * k4] = u.x;
        Xu[row * RSU + 2 * k4 + 1] = u.y;
    }
    for (int s = tid; s < 128 * 32; s += 256) {
        int row = s >> 5, k4 = s & 31;
        float4 v = *(const float4*)(g_Wc + (size_t)(n0 + row) * DIM + k4 * 4);
        ulonglong2 u = *(ulonglong2*)&v;
        Wu[row * RSU + 2 * k4] = u.x;
        Wu[row * RSU + 2 * k4 + 1] = u.y;
    }
    __syncthreads();

    const int tm = tid & 15;    // m rows tm+16*i
    const int tn = tid >> 4;    // n cols tn*8 .. +7

    ull acc[8][8];
    #pragma unroll
    for (int i = 0; i < 8; i++)
        #pragma unroll
        for (int n = 0; n < 8; n++) acc[i][n] = 0ull;

    #pragma unroll 4
    for (int k2 = 0; k2 < 64; k2++) {
        ull a[8], b[8];
        #pragma unroll
        for (int i = 0; i < 8; i++) a[i] = Xu[(tm + 16 * i) * RSU + k2];
        #pragma unroll
        for (int n = 0; n < 8; n++) b[n] = Wu[(tn * 8 + n) * RSU + k2];
        #pragma unroll
        for (int i = 0; i < 8; i++)
            #pragma unroll
            for (int n = 0; n < 8; n++)
                fma2(acc[i][n], a[i], b[n]);
    }

    float bcv[8];
    #pragma unroll
    for (int n = 0; n < 8; n++) bcv[n] = g_bc[n0 + tn * 8 + n];

    #pragma unroll
    for (int i = 0; i < 8; i++) {
        size_t base = (size_t)(m0 + tm + 16 * i) * GATES + n0 + tn * 8;
        float o[8];
        #pragma unroll
        for (int n = 0; n < 8; n++) o[n] = sum2(acc[i][n]) + bcv[n];
        *(float4*)(g_GI + base) = make_float4(o[0], o[1], o[2], o[3]);
        *(float4*)(g_GI + base + 4) = make_float4(o[4], o[5], o[6], o[7]);
    }
}

// ---------------- persistent GRU scan: 128 blocks x 4 batch rows ----------------
#define SSMEM ((32 * GATES * 4 + 4 * DIM) * 4)

__global__ __launch_bounds__(128, 1)
void gru_scan_kernel(const float* __restrict__ b_hh, float* __restrict__ out) {
    extern __shared__ float sm[];
    float* wq = sm;                      // 192 KB: [k4][col][4]
    float* hs = sm + 32 * GATES * 4;     // [4][128]

    const int j = threadIdx.x;
    const int r0 = blockIdx.x * 4;

    for (int s = j; s < 32 * GATES; s += 128)
        ((float4*)wq)[s] = ((const float4*)g_Wq)[s];

    #pragma unroll
    for (int row = 0; row < 4; row++) hs[row * DIM + j] = 0.f;
    __syncthreads();

    const float bh0 = b_hh[j], bh1 = b_hh[j + DIM], bh2 = b_hh[j + 2 * DIM];
    float hreg[4] = {0.f, 0.f, 0.f, 0.f};

    for (int t = 0; t < T_STEPS; t++) {
        float gi0[4], gi1[4], gi2[4];
        #pragma unroll
        for (int row = 0; row < 4; row++) {
            size_t base = ((size_t)t * BATCH + r0 + row) * GATES + j;
            gi0[row] = g_GI[base];
            gi1[row] = g_GI[base + DIM];
            gi2[row] = g_GI[base + 2 * DIM];
        }

        ull aR[4] = {0, 0, 0, 0}, aZ[4] = {0, 0, 0, 0}, aN[4] = {0, 0, 0, 0};

        #pragma unroll 4
        for (int k4 = 0; k4 < 32; k4++) {
            const ulonglong2* wp = (const ulonglong2*)(wq + (k4 * GATES + j) * 4);
            ulonglong2 w0 = wp[0];
            ulonglong2 w1 = wp[128];
            ulonglong2 w2 = wp[256];
            const ulonglong2* hp = (const ulonglong2*)hs;
            #pragma unroll
            for (int row = 0; row < 4; row++) {
                ulonglong2 hv = hp[row * 32 + k4];
                fma2(aR[row], w0.x, hv.x); fma2(aR[row], w0.y, hv.y);
                fma2(aZ[row], w1.x, hv.x); fma2(aZ[row], w1.y, hv.y);
                fma2(aN[row], w2.x, hv.x); fma2(aN[row], w2.y, hv.y);
            }
        }

        float hn[4];
        #pragma unroll
        for (int row = 0; row < 4; row++) {
            float r = sigm(sum2(aR[row]) + bh0 + gi0[row]);
            float z = sigm(sum2(aZ[row]) + bh1 + gi1[row]);
            float arg = gi2[row] + r * (sum2(aN[row]) + bh2);
            float n = 2.f * sigm(2.f * arg) - 1.f;   // tanh(arg)
            hn[row] = n + z * (hreg[row] - n);
        }
        __syncthreads();   // all reads of hs done
        #pragma unroll
        for (int row = 0; row < 4; row++) {
            hreg[row] = hn[row];
            hs[row * DIM + j] = hn[row];
        }
        __syncthreads();   // writes visible for next step
    }

    #pragma unroll
    for (int row = 0; row < 4; row++)
        out[(r0 + row) * DIM + j] = hreg[row];
}

// ---------------- launch ----------------
extern "C" void kernel_launch(void* const* d_in, const int* in_sizes, int n_in,
                              void* d_out, int out_size) {
    const float* x    = (const float*)d_in[0];
    const float* W1   = (const float*)d_in[1];
    const float* b1   = (const float*)d_in[2];
    const float* W_ih = (const float*)d_in[3];
    const float* W_hh = (const float*)d_in[4];
    const float* b_ih = (const float*)d_in[5];
    const float* b_hh = (const float*)d_in[6];
    float* out = (float*)d_out;

    static bool attr_done = false;
    if (!attr_done) {
        cudaFuncSetAttribute(gi_gemm_kernel,
                             cudaFuncAttributeMaxDynamicSharedMemorySize, GSMEM);
        cudaFuncSetAttribute(gru_scan_kernel,
                             cudaFuncAttributeMaxDynamicSharedMemorySize, SSMEM);
        attr_done = true;
    }

    prep_kernel<<<2 * GATES, DIM>>>(W1, b1, W_ih, W_hh, b_ih);
    dim3 ggrid(T_STEPS * BATCH / 128, GATES / 128);
    gi_gemm_kernel<<<ggrid, 256, GSMEM>>>(x);
    gru_scan_kernel<<<128, 128, SSMEM>>>(b_hh, out);
}

// round 3
// speedup vs baseline: 1.1436x; 1.1436x over previous
#include <cuda_runtime.h>
#include <cstdint>

#define T_STEPS 1024
#define BATCH   512
#define DIM     128
#define GATES   384
#define RSU     65

typedef unsigned long long ull;

__device__ float g_Wc[GATES * DIM];
__device__ float g_bc[GATES];
__device__ ull   g_Wrz[2 * 2 * 32 * 128];                // [gate r/z][half][kpair][j] f32x2
__device__ float g_Wn4[32 * 128 * 4];                    // [k4][j][4]
__device__ float g_GI[(size_t)T_STEPS * BATCH * GATES];  // 805 MB scratch

__device__ __forceinline__ void fma2(ull& acc, ull a, ull b) {
    asm("fma.rn.f32x2 %0, %1, %2, %0;" : "+l"(acc) : "l"(a), "l"(b));
}
__device__ __forceinline__ float sum2(ull v) {
    unsigned lo, hi;
    asm("mov.b64 {%0,%1}, %2;" : "=r"(lo), "=r"(hi) : "l"(v));
    return __uint_as_float(lo) + __uint_as_float(hi);
}
__device__ __forceinline__ float tanhf_fast(float x) {
    float y;
    asm("tanh.approx.f32 %0, %1;" : "=f"(y) : "f"(x));
    return y;
}
__device__ __forceinline__ float sigm_fast(float x) {
    return fmaf(0.5f, tanhf_fast(0.5f * x), 0.5f);
}

// ---------------- prep: fold fc1, repack W_hh ----------------
__global__ void prep_kernel(const float* __restrict__ W1, const float* __restrict__ b1,
                            const float* __restrict__ W_ih, const float* __restrict__ W_hh,
                            const float* __restrict__ b_ih) {
    int bid = blockIdx.x, tid = threadIdx.x;
    if (bid < GATES) {
        __shared__ float wih[DIM];
        __shared__ float red[DIM];
        wih[tid] = W_ih[bid * DIM + tid];
        __syncthreads();
        float acc = 0.f;
        #pragma unroll 8
        for (int k = 0; k < DIM; k++)
            acc = fmaf(wih[k], W1[k * DIM + tid], acc);
        g_Wc[bid * DIM + tid] = acc;
        red[tid] = wih[tid] * b1[tid];
        __syncthreads();
        if (tid == 0) {
            float s = 0.f;
            for (int k = 0; k < DIM; k++) s += red[k];
            g_bc[bid] = s + b_ih[bid];
        }
    } else {
        int col = bid - GATES;   // 0..383
        int k = tid;             // 0..127
        if (col < 256) {
            int g = col >> 7, j = col & 127;         // gates r(0), z(1)
            int half = k >> 6, kp = (k & 63) >> 1;
            float* dst = (float*)&g_Wrz[((g * 2 + half) * 32 + kp) * 128 + j];
            dst[k & 1] = W_hh[(g * DIM + j) * DIM + k];
        } else {
            int j = col - 256;                       // gate n
            g_Wn4[((k >> 2) * 128 + j) * 4 + (k & 3)] = W_hh[(2 * DIM + j) * DIM + k];
        }
    }
}

// ---------------- GI = X @ Wc^T + bc  (M=524288, N=384, K=128) ----------------
#define GSMEM (2 * 128 * 130 * 4)

__global__ __launch_bounds__(256, 1)
void gi_gemm_kernel(const float* __restrict__ X) {
    extern __shared__ float sm[];
    ull* Xu = (ull*)sm;
    ull* Wu = (ull*)(sm + 128 * 130);

    const int m0 = blockIdx.x * 128;
    const int n0 = blockIdx.y * 128;
    const int tid = threadIdx.x;

    for (int s = tid; s < 128 * 32; s += 256) {
        int row = s >> 5, k4 = s & 31;
        float4 v = *(const float4*)(X + (size_t)(m0 + row) * DIM + k4 * 4);
        ulonglong2 u = *(ulonglong2*)&v;
        Xu[row * RSU + 2 * k4] = u.x;
        Xu[row * RSU + 2 * k4 + 1] = u.y;
    }
    for (int s = tid; s < 128 * 32; s += 256) {
        int row = s >> 5, k4 = s & 31;
        float4 v = *(const float4*)(g_Wc + (size_t)(n0 + row) * DIM + k4 * 4);
        ulonglong2 u = *(ulonglong2*)&v;
        Wu[row * RSU + 2 * k4] = u.x;
        Wu[row * RSU + 2 * k4 + 1] = u.y;
    }
    __syncthreads();

    const int tm = tid & 15;
    const int tn = tid >> 4;

    ull acc[8][8];
    #pragma unroll
    for (int i = 0; i < 8; i++)
        #pragma unroll
        for (int n = 0; n < 8; n++) acc[i][n] = 0ull;

    #pragma unroll 4
    for (int k2 = 0; k2 < 64; k2++) {
        ull a[8], b[8];
        #pragma unroll
        for (int i = 0; i < 8; i++) a[i] = Xu[(tm + 16 * i) * RSU + k2];
        #pragma unroll
        for (int n = 0; n < 8; n++) b[n] = Wu[(tn * 8 + n) * RSU + k2];
        #pragma unroll
        for (int i = 0; i < 8; i++)
            #pragma unroll
            for (int n = 0; n < 8; n++)
                fma2(acc[i][n], a[i], b[n]);
    }

    float bcv[8];
    #pragma unroll
    for (int n = 0; n < 8; n++) bcv[n] = g_bc[n0 + tn * 8 + n];

    #pragma unroll
    for (int i = 0; i < 8; i++) {
        size_t base = (size_t)(m0 + tm + 16 * i) * GATES + n0 + tn * 8;
        float o[8];
        #pragma unroll
        for (int n = 0; n < 8; n++) o[n] = sum2(acc[i][n]) + bcv[n];
        *(float4*)(g_GI + base) = make_float4(o[0], o[1], o[2], o[3]);
        *(float4*)(g_GI + base + 4) = make_float4(o[4], o[5], o[6], o[7]);
    }
}

// ---------------- persistent GRU scan v2: regs for W_r/W_z, k-split ----------------
// 128 blocks x 4 batch rows; 256 threads = (j 0..127) x (khalf 0..1)
#define WN_F   (32 * 128 * 4)            // 16384 floats (64 KB)
#define HS_F   (4 * 128)                 // 512
#define SC_F   (12 * 128)                // 1536
#define SSMEM  ((WN_F + HS_F + SC_F) * 4)

__global__ __launch_bounds__(256, 1)
void gru_scan_kernel(const float* __restrict__ b_hh, float* __restrict__ out) {
    extern __shared__ float sm[];
    float* wn = sm;                  // [k4][j][4]
    float* hs = sm + WN_F;           // [4][128]
    float* sc = sm + WN_F + HS_F;    // [12][128]

    const int tid = threadIdx.x;
    const int j = tid & 127;
    const int half = tid >> 7;       // warps 0-3: half 0, warps 4-7: half 1
    const int r0 = blockIdx.x * 4;

    // stage W_n into SMEM
    for (int s = tid; s < WN_F / 4; s += 256)
        ((float4*)wn)[s] = ((const float4*)g_Wn4)[s];

    // W_r, W_z into registers: 32 f32x2 pairs each (this thread's 64 k values)
    ull wr[32], wz[32];
    #pragma unroll
    for (int kp = 0; kp < 32; kp++) {
        wr[kp] = g_Wrz[((0 * 2 + half) * 32 + kp) * 128 + j];
        wz[kp] = g_Wrz[((1 * 2 + half) * 32 + kp) * 128 + j];
    }

    for (int s = tid; s < HS_F; s += 256) hs[s] = 0.f;
    __syncthreads();

    const float bh0 = b_hh[j], bh1 = b_hh[j + DIM], bh2 = b_hh[j + 2 * DIM];
    float hreg[4] = {0.f, 0.f, 0.f, 0.f};   // tracked by half 0

    for (int t = 0; t < T_STEPS; t++) {
        // prefetch this step's input gates (half 0 only; consumed in epilogue)
        float gi0[4], gi1[4], gi2[4];
        if (half == 0) {
            #pragma unroll
            for (int row = 0; row < 4; row++) {
                size_t base = ((size_t)t * BATCH + r0 + row) * GATES + j;
                gi0[row] = g_GI[base];
                gi1[row] = g_GI[base + DIM];
                gi2[row] = g_GI[base + 2 * DIM];
            }
        }

        ull aR[4] = {0, 0, 0, 0}, aZ[4] = {0, 0, 0, 0}, aN[4] = {0, 0, 0, 0};

        #pragma unroll
        for (int k16 = 0; k16 < 16; k16++) {
            int k4 = half * 16 + k16;             // global 4-k group
            ulonglong2 wnv = *(const ulonglong2*)(wn + (k4 * 128 + j) * 4);
            const ulonglong2* hp = (const ulonglong2*)hs;
            #pragma unroll
            for (int row = 0; row < 4; row++) {
                ulonglong2 hv = hp[row * 32 + k4];      // broadcast LDS.128
                fma2(aR[row], wr[2 * k16],     hv.x);
                fma2(aR[row], wr[2 * k16 + 1], hv.y);
                fma2(aZ[row], wz[2 * k16],     hv.x);
                fma2(aZ[row], wz[2 * k16 + 1], hv.y);
                fma2(aN[row], wnv.x, hv.x);
                fma2(aN[row], wnv.y, hv.y);
            }
        }

        // half 1 publishes partials
        if (half == 1) {
            #pragma unroll
            for (int row = 0; row < 4; row++) {
                sc[(0 * 4 + row) * 128 + j] = sum2(aR[row]);
                sc[(1 * 4 + row) * 128 + j] = sum2(aZ[row]);
                sc[(2 * 4 + row) * 128 + j] = sum2(aN[row]);
            }
        }
        __syncthreads();   // partials visible; all hs reads done

        if (half == 0) {
            #pragma unroll
            for (int row = 0; row < 4; row++) {
                float pR = sum2(aR[row]) + sc[(0 * 4 + row) * 128 + j];
                float pZ = sum2(aZ[row]) + sc[(1 * 4 + row) * 128 + j];
                float pN = sum2(aN[row]) + sc[(2 * 4 + row) * 128 + j];
                float r = sigm_fast(pR + bh0 + gi0[row]);
                float z = sigm_fast(pZ + bh1 + gi1[row]);
                float n = tanhf_fast(gi2[row] + r * (pN + bh2));
                float h = n + z * (hreg[row] - n);
                hreg[row] = h;
                hs[row * DIM + j] = h;
            }
        }
        __syncthreads();   // new h visible for next step
    }

    if (half == 0) {
        #pragma unroll
        for (int row = 0; row < 4; row++)
            out[(r0 + row) * DIM + j] = hreg[row];
    }
}

// ---------------- launch ----------------
extern "C" void kernel_launch(void* const* d_in, const int* in_sizes, int n_in,
                              void* d_out, int out_size) {
    const float* x    = (const float*)d_in[0];
    const float* W1   = (const float*)d_in[1];
    const float* b1   = (const float*)d_in[2];
    const float* W_ih = (const float*)d_in[3];
    const float* W_hh = (const float*)d_in[4];
    const float* b_ih = (const float*)d_in[5];
    const float* b_hh = (const float*)d_in[6];
    float* out = (float*)d_out;

    static bool attr_done = false;
    if (!attr_done) {
        cudaFuncSetAttribute(gi_gemm_kernel,
                             cudaFuncAttributeMaxDynamicSharedMemorySize, GSMEM);
        cudaFuncSetAttribute(gru_scan_kernel,
                             cudaFuncAttributeMaxDynamicSharedMemorySize, SSMEM);
        attr_done = true;
    }

    prep_kernel<<<2 * GATES, DIM>>>(W1, b1, W_ih, W_hh, b_ih);
    dim3 ggrid(T_STEPS * BATCH / 128, GATES / 128);
    gi_gemm_kernel<<<ggrid, 256, GSMEM>>>(x);
    gru_scan_kernel<<<128, 256, SSMEM>>>(b_hh, out);
}

// round 5
// speedup vs baseline: 1.7639x; 1.5424x over previous
#include <cuda_runtime.h>
#include <cuda_bf16.h>
#include <cstdint>

#define T_STEPS 1024
#define BATCH   512
#define DIM     128
#define GATES   384

typedef unsigned long long ull;

// ---------------- device scratch ----------------
__device__ float g_bc[GATES];
__device__ ull   g_Wrz[2 * 2 * 32 * 128];                // scan: [gate r/z][half][kpair][j]
__device__ float g_Wn4[32 * 128 * 4];                    // scan: [k4][j][4]
__device__ __nv_bfloat16 g_Bh[3 * 16384];                // Wc hi: [nt][row][k] plain
__device__ __nv_bfloat16 g_Bl[3 * 16384];                // Wc lo
__device__ float g_GI[(size_t)T_STEPS * BATCH * GATES];  // 805 MB scratch

// ---------------- helpers ----------------
__device__ __forceinline__ void fma2(ull& acc, ull a, ull b) {
    asm("fma.rn.f32x2 %0, %1, %2, %0;" : "+l"(acc) : "l"(a), "l"(b));
}
__device__ __forceinline__ float sum2(ull v) {
    unsigned lo, hi;
    asm("mov.b64 {%0,%1}, %2;" : "=r"(lo), "=r"(hi) : "l"(v));
    return __uint_as_float(lo) + __uint_as_float(hi);
}
__device__ __forceinline__ float tanhf_fast(float x) {
    float y; asm("tanh.approx.f32 %0, %1;" : "=f"(y) : "f"(x)); return y;
}
__device__ __forceinline__ float sigm_fast(float x) {
    return fmaf(0.5f, tanhf_fast(0.5f * x), 0.5f);
}
__device__ __forceinline__ uint32_t smem_u32(const void* p) {
    uint32_t a;
    asm("{ .reg .u64 t; cvta.to.shared.u64 t, %1; cvt.u32.u64 %0, t; }" : "=r"(a) : "l"(p));
    return a;
}
__device__ __forceinline__ void ldsm4(uint32_t& r0, uint32_t& r1, uint32_t& r2, uint32_t& r3,
                                      uint32_t addr) {
    asm volatile("ldmatrix.sync.aligned.m8n8.x4.shared.b16 {%0,%1,%2,%3}, [%4];"
                 : "=r"(r0), "=r"(r1), "=r"(r2), "=r"(r3) : "r"(addr));
}
__device__ __forceinline__ void mma16816(float* c, const uint32_t* a, uint32_t b0, uint32_t b1) {
    asm volatile(
        "mma.sync.aligned.m16n8k16.row.col.f32.bf16.bf16.f32 "
        "{%0,%1,%2,%3}, {%4,%5,%6,%7}, {%8,%9}, {%0,%1,%2,%3};"
        : "+f"(c[0]), "+f"(c[1]), "+f"(c[2]), "+f"(c[3])
        : "r"(a[0]), "r"(a[1]), "r"(a[2]), "r"(a[3]), "r"(b0), "r"(b1));
}

// ---------------- prep: fold fc1 into Wc (bf16 hi/lo) + scan weights ----------------
__global__ void prep_kernel(const float* __restrict__ W1, const float* __restrict__ b1,
                            const float* __restrict__ W_ih, const float* __restrict__ W_hh,
                            const float* __restrict__ b_ih) {
    int bid = blockIdx.x, tid = threadIdx.x;
    if (bid < GATES) {
        __shared__ float wih[DIM];
        __shared__ float red[DIM];
        wih[tid] = W_ih[bid * DIM + tid];
        __syncthreads();
        float acc = 0.f;
        #pragma unroll 8
        for (int k = 0; k < DIM; k++)
            acc = fmaf(wih[k], W1[k * DIM + tid], acc);
        __nv_bfloat16 h = __float2bfloat16(acc);
        __nv_bfloat16 l = __float2bfloat16(acc - __bfloat162float(h));
        g_Bh[bid * DIM + tid] = h;   // [nt*128 + row][k] == nt*16384 + row*128 + k
        g_Bl[bid * DIM + tid] = l;
        red[tid] = wih[tid] * b1[tid];
        __syncthreads();
        if (tid == 0) {
            float s = 0.f;
            for (int k = 0; k < DIM; k++) s += red[k];
            g_bc[bid] = s + b_ih[bid];
        }
    } else {
        int col = bid - GATES;
        int k = tid;
        if (col < 256) {
            int g = col >> 7, j = col & 127;
            int half = k >> 6, kp = (k & 63) >> 1;
            float* dst = (float*)&g_Wrz[((g * 2 + half) * 32 + kp) * 128 + j];
            dst[k & 1] = W_hh[(g * DIM + j) * DIM + k];
        } else {
            int j = col - 256;
            g_Wn4[((k >> 2) * 128 + j) * 4 + (k & 3)] = W_hh[(2 * DIM + j) * DIM + k];
        }
    }
}

// ---------------- HMMA GI GEMM: GI = X @ Wc^T + bc ----------------
// grid (3, 8192): nt fastest (A-tile L2 reuse). Block = 64 x 128 tile.
// SMEM rows padded to 136 bf16 (272 B = 16*17): 16B-aligned + ldmatrix conflict-free.
#define PAD 136
#define GSM_BC  0
#define GSM_AH  1024
#define GSM_AL  (GSM_AH + 64 * PAD * 2)       // +17408
#define GSM_BH  (GSM_AL + 64 * PAD * 2)
#define GSM_BL  (GSM_BH + 128 * PAD * 2)      // +34816
#define GSMEM   (GSM_BL + 128 * PAD * 2)

__global__ __launch_bounds__(256, 1)
void gi_gemm_hmma(const float* __restrict__ X) {
    extern __shared__ char smem[];
    const uint32_t sbase = smem_u32(smem);
    const int tid = threadIdx.x;
    const int wid = tid >> 5, lane = tid & 31;
    const int nt = blockIdx.x;
    const int n0 = nt * 128;
    const int m0 = blockIdx.y * 64;

    // ---- stage A (fp32 -> bf16 hi/lo, padded) ----
    const float4* Xf4 = (const float4*)X;
    #pragma unroll 4
    for (int s = tid; s < 2048; s += 256) {
        int row = s >> 5, q = s & 31;
        float4 v = Xf4[(size_t)(m0 + row) * 32 + q];
        __nv_bfloat16 h0 = __float2bfloat16(v.x), h1 = __float2bfloat16(v.y);
        __nv_bfloat16 h2 = __float2bfloat16(v.z), h3 = __float2bfloat16(v.w);
        __nv_bfloat16 l0 = __float2bfloat16(v.x - __bfloat162float(h0));
        __nv_bfloat16 l1 = __float2bfloat16(v.y - __bfloat162float(h1));
        __nv_bfloat16 l2 = __float2bfloat16(v.z - __bfloat162float(h2));
        __nv_bfloat16 l3 = __float2bfloat16(v.w - __bfloat162float(h3));
        __nv_bfloat162 hA(h0, h1), hB(h2, h3), lA(l0, l1), lB(l2, l3);
        int off = row * 272 + q * 8;
        *(uint2*)(smem + GSM_AH + off) = make_uint2(*(uint32_t*)&hA, *(uint32_t*)&hB);
        *(uint2*)(smem + GSM_AL + off) = make_uint2(*(uint32_t*)&lA, *(uint32_t*)&lB);
    }
    // ---- stage B (bf16, padded) ----
    const uint4* Bh4 = (const uint4*)(g_Bh + nt * 16384);
    const uint4* Bl4 = (const uint4*)(g_Bl + nt * 16384);
    #pragma unroll 4
    for (int s = tid; s < 2048; s += 256) {
        int row = s >> 4, u = s & 15;
        int off = row * 272 + u * 16;
        *(uint4*)(smem + GSM_BH + off) = Bh4[s];
        *(uint4*)(smem + GSM_BL + off) = Bl4[s];
    }
    if (tid < 128) *(float*)(smem + GSM_BC + tid * 4) = g_bc[n0 + tid];
    __syncthreads();

    // ---- warp tiling: 2 (m) x 4 (n) warps; warp tile 32x32 ----
    const int wm = wid & 1;
    const int wn = wid >> 1;

    // ldmatrix lane address components (byte offsets within tile)
    const uint32_t aoff = (uint32_t)(wm * 32 + (lane & 15)) * 272 + ((lane >> 4) << 4);
    const uint32_t boff = (uint32_t)(wn * 32 + (lane & 7) + ((lane >> 4) << 3)) * 272
                        + (((lane >> 3) & 1) << 4);

    float C[2][4][4];
    #pragma unroll
    for (int mf = 0; mf < 2; mf++)
        #pragma unroll
        for (int nf = 0; nf < 4; nf++)
            #pragma unroll
            for (int q = 0; q < 4; q++) C[mf][nf][q] = 0.f;

    const uint32_t abase[3] = { sbase + GSM_AH, sbase + GSM_AH, sbase + GSM_AL };
    const uint32_t bbase[3] = { sbase + GSM_BH, sbase + GSM_BL, sbase + GSM_BH };

    #pragma unroll
    for (int p = 0; p < 3; p++) {
        const uint32_t ab = abase[p] + aoff;
        const uint32_t bb = bbase[p] + boff;
        #pragma unroll
        for (int ks = 0; ks < 8; ks++) {
            uint32_t a[2][4], b[2][4];
            ldsm4(a[0][0], a[0][1], a[0][2], a[0][3], ab + ks * 32);
            ldsm4(a[1][0], a[1][1], a[1][2], a[1][3], ab + 16 * 272 + ks * 32);
            ldsm4(b[0][0], b[0][1], b[0][2], b[0][3], bb + ks * 32);
            ldsm4(b[1][0], b[1][1], b[1][2], b[1][3], bb + 16 * 272 + ks * 32);
            #pragma unroll
            for (int mf = 0; mf < 2; mf++) {
                mma16816(C[mf][0], a[mf], b[0][0], b[0][1]);
                mma16816(C[mf][1], a[mf], b[0][2], b[0][3]);
                mma16816(C[mf][2], a[mf], b[1][0], b[1][1]);
                mma16816(C[mf][3], a[mf], b[1][2], b[1][3]);
            }
        }
    }

    // ---- epilogue: add bc, store float2 pairs ----
    const float* bcs = (const float*)(smem + GSM_BC);
    const int qrow = lane >> 2, qcol = (lane & 3) * 2;
    #pragma unroll
    for (int mf = 0; mf < 2; mf++) {
        int row = m0 + wm * 32 + mf * 16 + qrow;
        #pragma unroll
        for (int nf = 0; nf < 4; nf++) {
            int colL = wn * 32 + nf * 8 + qcol;
            float b0 = bcs[colL], b1 = bcs[colL + 1];
            float* d0 = g_GI + (size_t)row * GATES + n0 + colL;
            *(float2*)d0 = make_float2(C[mf][nf][0] + b0, C[mf][nf][1] + b1);
            float* d1 = g_GI + (size_t)(row + 8) * GATES + n0 + colL;
            *(float2*)d1 = make_float2(C[mf][nf][2] + b0, C[mf][nf][3] + b1);
        }
    }
}

// ---------------- persistent GRU scan (unchanged) ----------------
#define WN_F   (32 * 128 * 4)
#define HS_F   (4 * 128)
#define SC_F   (12 * 128)
#define SSMEM  ((WN_F + HS_F + SC_F) * 4)

__global__ __launch_bounds__(256, 1)
void gru_scan_kernel(const float* __restrict__ b_hh, float* __restrict__ out) {
    extern __shared__ float sm[];
    float* wn = sm;
    float* hs = sm + WN_F;
    float* sc = sm + WN_F + HS_F;

    const int tid = threadIdx.x;
    const int j = tid & 127;
    const int half = tid >> 7;
    const int r0 = blockIdx.x * 4;

    for (int s = tid; s < WN_F / 4; s += 256)
        ((float4*)wn)[s] = ((const float4*)g_Wn4)[s];

    ull wr[32], wz[32];
    #pragma unroll
    for (int kp = 0; kp < 32; kp++) {
        wr[kp] = g_Wrz[((0 * 2 + half) * 32 + kp) * 128 + j];
        wz[kp] = g_Wrz[((1 * 2 + half) * 32 + kp) * 128 + j];
    }

    for (int s = tid; s < HS_F; s += 256) hs[s] = 0.f;
    __syncthreads();

    const float bh0 = b_hh[j], bh1 = b_hh[j + DIM], bh2 = b_hh[j + 2 * DIM];
    float hreg[4] = {0.f, 0.f, 0.f, 0.f};

    for (int t = 0; t < T_STEPS; t++) {
        float gi0[4], gi1[4], gi2[4];
        if (half == 0) {
            #pragma unroll
            for (int row = 0; row < 4; row++) {
                size_t base = ((size_t)t * BATCH + r0 + row) * GATES + j;
                gi0[row] = g_GI[base];
                gi1[row] = g_GI[base + DIM];
                gi2[row] = g_GI[base + 2 * DIM];
            }
        }

        ull aR[4] = {0, 0, 0, 0}, aZ[4] = {0, 0, 0, 0}, aN[4] = {0, 0, 0, 0};

        #pragma unroll
        for (int k16 = 0; k16 < 16; k16++) {
            int k4 = half * 16 + k16;
            ulonglong2 wnv = *(const ulonglong2*)(wn + (k4 * 128 + j) * 4);
            const ulonglong2* hp = (const ulonglong2*)hs;
            #pragma unroll
            for (int row = 0; row < 4; row++) {
                ulonglong2 hv = hp[row * 32 + k4];
                fma2(aR[row], wr[2 * k16],     hv.x);
                fma2(aR[row], wr[2 * k16 + 1], hv.y);
                fma2(aZ[row], wz[2 * k16],     hv.x);
                fma2(aZ[row], wz[2 * k16 + 1], hv.y);
                fma2(aN[row], wnv.x, hv.x);
                fma2(aN[row], wnv.y, hv.y);
            }
        }

        if (half == 1) {
            #pragma unroll
            for (int row = 0; row < 4; row++) {
                sc[(0 * 4 + row) * 128 + j] = sum2(aR[row]);
                sc[(1 * 4 + row) * 128 + j] = sum2(aZ[row]);
                sc[(2 * 4 + row) * 128 + j] = sum2(aN[row]);
            }
        }
        __syncthreads();

        if (half == 0) {
            #pragma unroll
            for (int row = 0; row < 4; row++) {
                float pR = sum2(aR[row]) + sc[(0 * 4 + row) * 128 + j];
                float pZ = sum2(aZ[row]) + sc[(1 * 4 + row) * 128 + j];
                float pN = sum2(aN[row]) + sc[(2 * 4 + row) * 128 + j];
                float r = sigm_fast(pR + bh0 + gi0[row]);
                float z = sigm_fast(pZ + bh1 + gi1[row]);
                float n = tanhf_fast(gi2[row] + r * (pN + bh2));
                float h = n + z * (hreg[row] - n);
                hreg[row] = h;
                hs[row * DIM + j] = h;
            }
        }
        __syncthreads();
    }

    if (half == 0) {
        #pragma unroll
        for (int row = 0; row < 4; row++)
            out[(r0 + row) * DIM + j] = hreg[row];
    }
}

// ---------------- launch ----------------
extern "C" void kernel_launch(void* const* d_in, const int* in_sizes, int n_in,
                              void* d_out, int out_size) {
    const float* x    = (const float*)d_in[0];
    const float* W1   = (const float*)d_in[1];
    const float* b1   = (const float*)d_in[2];
    const float* W_ih = (const float*)d_in[3];
    const float* W_hh = (const float*)d_in[4];
    const float* b_ih = (const float*)d_in[5];
    const float* b_hh = (const float*)d_in[6];
    float* out = (float*)d_out;

    static bool attr_done = false;
    if (!attr_done) {
        cudaFuncSetAttribute(gi_gemm_hmma,
                             cudaFuncAttributeMaxDynamicSharedMemorySize, GSMEM);
        cudaFuncSetAttribute(gru_scan_kernel,
                             cudaFuncAttributeMaxDynamicSharedMemorySize, SSMEM);
        attr_done = true;
    }

    prep_kernel<<<2 * GATES, DIM>>>(W1, b1, W_ih, W_hh, b_ih);
    gi_gemm_hmma<<<dim3(3, 8192), 256, GSMEM>>>(x);
    gru_scan_kernel<<<128, 256, SSMEM>>>(b_hh, out);
}

// round 6
// speedup vs baseline: 1.8764x; 1.0638x over previous
#include <cuda_runtime.h>
#include <cuda_bf16.h>
#include <cstdint>

#define T_STEPS 1024
#define BATCH   512
#define DIM     128
#define GATES   384

// ---------------- device scratch ----------------
__device__ float g_bc[GATES];
__device__ __nv_bfloat16 g_Bh[3 * 16384];                // Wc hi: [nt][row][k]
__device__ __nv_bfloat16 g_Bl[3 * 16384];                // Wc lo
__device__ float g_GI[(size_t)T_STEPS * BATCH * GATES];  // 805 MB scratch

// ---------------- helpers ----------------
__device__ __forceinline__ float tanhf_fast(float x) {
    float y; asm("tanh.approx.f32 %0, %1;" : "=f"(y) : "f"(x)); return y;
}
__device__ __forceinline__ float sigm_fast(float x) {
    return fmaf(0.5f, tanhf_fast(0.5f * x), 0.5f);
}
__device__ __forceinline__ uint32_t smem_u32(const void* p) {
    uint32_t a;
    asm("{ .reg .u64 t; cvta.to.shared.u64 t, %1; cvt.u32.u64 %0, t; }" : "=r"(a) : "l"(p));
    return a;
}
__device__ __forceinline__ void ldsm4(uint32_t& r0, uint32_t& r1, uint32_t& r2, uint32_t& r3,
                                      uint32_t addr) {
    asm volatile("ldmatrix.sync.aligned.m8n8.x4.shared.b16 {%0,%1,%2,%3}, [%4];"
                 : "=r"(r0), "=r"(r1), "=r"(r2), "=r"(r3) : "r"(addr));
}
__device__ __forceinline__ void ldsm2t(uint32_t& r0, uint32_t& r1, uint32_t addr) {
    asm volatile("ldmatrix.sync.aligned.m8n8.x2.trans.shared.b16 {%0,%1}, [%2];"
                 : "=r"(r0), "=r"(r1) : "r"(addr));
}
__device__ __forceinline__ void mma16816(float* c, const uint32_t* a, uint32_t b0, uint32_t b1) {
    asm volatile(
        "mma.sync.aligned.m16n8k16.row.col.f32.bf16.bf16.f32 "
        "{%0,%1,%2,%3}, {%4,%5,%6,%7}, {%8,%9}, {%0,%1,%2,%3};"
        : "+f"(c[0]), "+f"(c[1]), "+f"(c[2]), "+f"(c[3])
        : "r"(a[0]), "r"(a[1]), "r"(a[2]), "r"(a[3]), "r"(b0), "r"(b1));
}
__device__ __forceinline__ void split_bf16(float v, __nv_bfloat16& h, __nv_bfloat16& l) {
    h = __float2bfloat16(v);
    l = __float2bfloat16(v - __bfloat162float(h));
}

// ---------------- prep: fold fc1 into Wc (bf16 hi/lo) + bc ----------------
__global__ void prep_kernel(const float* __restrict__ W1, const float* __restrict__ b1,
                            const float* __restrict__ W_ih, const float* __restrict__ b_ih) {
    int bid = blockIdx.x, tid = threadIdx.x;
    __shared__ float wih[DIM];
    __shared__ float red[DIM];
    wih[tid] = W_ih[bid * DIM + tid];
    __syncthreads();
    float acc = 0.f;
    #pragma unroll 8
    for (int k = 0; k < DIM; k++)
        acc = fmaf(wih[k], W1[k * DIM + tid], acc);
    __nv_bfloat16 h, l;
    split_bf16(acc, h, l);
    g_Bh[bid * DIM + tid] = h;
    g_Bl[bid * DIM + tid] = l;
    red[tid] = wih[tid] * b1[tid];
    __syncthreads();
    if (tid == 0) {
        float s = 0.f;
        for (int k = 0; k < DIM; k++) s += red[k];
        g_bc[bid] = s + b_ih[bid];
    }
}

// ---------------- HMMA GI GEMM: GI = X @ Wc^T + bc ----------------
#define GSM_BC  0
#define GSM_AH  1024
#define GSM_AL  (GSM_AH + 64 * 272)
#define GSM_BH  (GSM_AL + 64 * 272)
#define GSM_BL  (GSM_BH + 128 * 272)
#define GSMEM   (GSM_BL + 128 * 272)

__global__ __launch_bounds__(256, 2)
void gi_gemm_hmma(const float* __restrict__ X) {
    extern __shared__ char smem[];
    const uint32_t sbase = smem_u32(smem);
    const int tid = threadIdx.x;
    const int wid = tid >> 5, lane = tid & 31;
    const int nt = blockIdx.x;
    const int n0 = nt * 128;
    const int m0 = blockIdx.y * 64;

    // stage A (fp32 -> bf16 hi/lo, 272B-padded rows)
    const float4* Xf4 = (const float4*)X;
    #pragma unroll 4
    for (int s = tid; s < 2048; s += 256) {
        int row = s >> 5, q = s & 31;
        float4 v = Xf4[(size_t)(m0 + row) * 32 + q];
        __nv_bfloat16 h0, h1, h2, h3, l0, l1, l2, l3;
        split_bf16(v.x, h0, l0); split_bf16(v.y, h1, l1);
        split_bf16(v.z, h2, l2); split_bf16(v.w, h3, l3);
        __nv_bfloat162 hA(h0, h1), hB(h2, h3), lA(l0, l1), lB(l2, l3);
        int off = row * 272 + q * 8;
        *(uint2*)(smem + GSM_AH + off) = make_uint2(*(uint32_t*)&hA, *(uint32_t*)&hB);
        *(uint2*)(smem + GSM_AL + off) = make_uint2(*(uint32_t*)&lA, *(uint32_t*)&lB);
    }
    // stage B
    const uint4* Bh4 = (const uint4*)(g_Bh + nt * 16384);
    const uint4* Bl4 = (const uint4*)(g_Bl + nt * 16384);
    #pragma unroll 4
    for (int s = tid; s < 2048; s += 256) {
        int row = s >> 4, u = s & 15;
        int off = row * 272 + u * 16;
        *(uint4*)(smem + GSM_BH + off) = Bh4[s];
        *(uint4*)(smem + GSM_BL + off) = Bl4[s];
    }
    if (tid < 128) *(float*)(smem + GSM_BC + tid * 4) = g_bc[n0 + tid];
    __syncthreads();

    const int wm = wid & 1;
    const int wn = wid >> 1;
    const uint32_t aoff = (uint32_t)(wm * 32 + (lane & 15)) * 272 + ((lane >> 4) << 4);
    const uint32_t boff = (uint32_t)(wn * 32 + (lane & 7) + ((lane >> 4) << 3)) * 272
                        + (((lane >> 3) & 1) << 4);

    float C[2][4][4];
    #pragma unroll
    for (int mf = 0; mf < 2; mf++)
        #pragma unroll
        for (int nf = 0; nf < 4; nf++)
            #pragma unroll
            for (int q = 0; q < 4; q++) C[mf][nf][q] = 0.f;

    const uint32_t abase[3] = { sbase + GSM_AH, sbase + GSM_AH, sbase + GSM_AL };
    const uint32_t bbase[3] = { sbase + GSM_BH, sbase + GSM_BL, sbase + GSM_BH };

    #pragma unroll
    for (int p = 0; p < 3; p++) {
        const uint32_t ab = abase[p] + aoff;
        const uint32_t bb = bbase[p] + boff;
        #pragma unroll
        for (int ks = 0; ks < 8; ks++) {
            uint32_t a[2][4], b[2][4];
            ldsm4(a[0][0], a[0][1], a[0][2], a[0][3], ab + ks * 32);
            ldsm4(a[1][0], a[1][1], a[1][2], a[1][3], ab + 16 * 272 + ks * 32);
            ldsm4(b[0][0], b[0][1], b[0][2], b[0][3], bb + ks * 32);
            ldsm4(b[1][0], b[1][1], b[1][2], b[1][3], bb + 16 * 272 + ks * 32);
            #pragma unroll
            for (int mf = 0; mf < 2; mf++) {
                mma16816(C[mf][0], a[mf], b[0][0], b[0][1]);
                mma16816(C[mf][1], a[mf], b[0][2], b[0][3]);
                mma16816(C[mf][2], a[mf], b[1][0], b[1][1]);
                mma16816(C[mf][3], a[mf], b[1][2], b[1][3]);
            }
        }
    }

    const float* bcs = (const float*)(smem + GSM_BC);
    const int qrow = lane >> 2, qcol = (lane & 3) * 2;
    #pragma unroll
    for (int mf = 0; mf < 2; mf++) {
        int row = m0 + wm * 32 + mf * 16 + qrow;
        #pragma unroll
        for (int nf = 0; nf < 4; nf++) {
            int colL = wn * 32 + nf * 8 + qcol;
            float b0 = bcs[colL], b1 = bcs[colL + 1];
            float* d0 = g_GI + (size_t)row * GATES + n0 + colL;
            *(float2*)d0 = make_float2(C[mf][nf][0] + b0, C[mf][nf][1] + b1);
            float* d1 = g_GI + (size_t)(row + 8) * GATES + n0 + colL;
            *(float2*)d1 = make_float2(C[mf][nf][2] + b0, C[mf][nf][3] + b1);
        }
    }
}

// ---------------- HMMA GRU scan: 128 blocks x 4 batch rows (n8-padded) ----------------
// W_hh bf16 hi/lo in SMEM [384][272B]; h feedback bf16 hi/lo [k=j][b] 16B rows.
#define SW_HI  0
#define SW_LO  104448
#define SH_HI  208896
#define SH_LO  210944
#define S2SMEM 212992

__global__ __launch_bounds__(256, 1)
void gru_scan_hmma(const float* __restrict__ W_hh, const float* __restrict__ b_hh,
                   float* __restrict__ out) {
    extern __shared__ char smem[];
    const uint32_t sbase = smem_u32(smem);
    const int tid = threadIdx.x, w = tid >> 5, lane = tid & 31;
    const int r0 = blockIdx.x * 4;

    // stage W_hh -> bf16 hi/lo, 272B-padded rows
    #pragma unroll 4
    for (int s = tid; s < 12288; s += 256) {
        int row = s >> 5, q = s & 31;
        float4 v = ((const float4*)W_hh)[s];
        __nv_bfloat16 h0, h1, h2, h3, l0, l1, l2, l3;
        split_bf16(v.x, h0, l0); split_bf16(v.y, h1, l1);
        split_bf16(v.z, h2, l2); split_bf16(v.w, h3, l3);
        __nv_bfloat162 hA(h0, h1), hB(h2, h3), lA(l0, l1), lB(l2, l3);
        int off = row * 272 + q * 8;
        *(uint2*)(smem + SW_HI + off) = make_uint2(*(uint32_t*)&hA, *(uint32_t*)&hB);
        *(uint2*)(smem + SW_LO + off) = make_uint2(*(uint32_t*)&lA, *(uint32_t*)&lB);
    }
    // zero h (hi+lo = 4KB)
    for (int s = tid; s < 512; s += 256) {
        ((uint32_t*)(smem + SH_HI))[s] = 0;
        ((uint32_t*)(smem + SH_LO))[s] = 0;
    }

    // lane -> (j, c) mapping for D-frags
    const int jq = lane >> 2;
    const int j0 = 16 * w + jq, j1 = j0 + 8;
    const int c0 = 2 * (lane & 3);            // cols c0, c0+1; real batch iff c0 < 4
    const bool valid = (c0 < 4);

    const float br[2] = { b_hh[j0], b_hh[j1] };
    const float bz[2] = { b_hh[DIM + j0], b_hh[DIM + j1] };
    const float bn[2] = { b_hh[2 * DIM + j0], b_hh[2 * DIM + j1] };

    // A (W) ldmatrix base: rows 16w.. within gate block g at +g*128 rows
    const uint32_t a_base = sbase + SW_HI
        + (uint32_t)(16 * w + (lane & 15)) * 272 + ((lane >> 4) << 4);
    // B (h) ldmatrix base: rows = k
    const uint32_t bh_base = sbase + SH_HI + (uint32_t)(lane & 15) * 16;
    const uint32_t bl_base = sbase + SH_LO + (uint32_t)(lane & 15) * 16;

    float hprev[4] = {0.f, 0.f, 0.f, 0.f};

    for (int t = 0; t < T_STEPS; t++) {
        __syncthreads();   // h stores from previous step visible

        // prefetch input gates for this lane's (j, b) pairs
        float giv[3][4];
        #pragma unroll
        for (int q = 0; q < 4; q++) {
            if (valid) {
                int j = (q & 2) ? j1 : j0;
                int c = c0 + (q & 1);
                size_t base = ((size_t)t * BATCH + r0 + c) * GATES + j;
                giv[0][q] = g_GI[base];
                giv[1][q] = g_GI[base + DIM];
                giv[2][q] = g_GI[base + 2 * DIM];
            } else {
                giv[0][q] = giv[1][q] = giv[2][q] = 0.f;
            }
        }

        // B frags (h hi/lo) for all 8 k-steps
        uint32_t bhf[8][2], blf[8][2];
        #pragma unroll
        for (int ks = 0; ks < 8; ks++) {
            ldsm2t(bhf[ks][0], bhf[ks][1], bh_base + ks * 256);
            ldsm2t(blf[ks][0], blf[ks][1], bl_base + ks * 256);
        }

        float C[3][4];
        #pragma unroll
        for (int g = 0; g < 3; g++)
            #pragma unroll
            for (int q = 0; q < 4; q++) C[g][q] = 0.f;

        #pragma unroll
        for (int g = 0; g < 3; g++) {
            const uint32_t ag = a_base + (uint32_t)g * (128 * 272);
            #pragma unroll
            for (int ks = 0; ks < 8; ks++) {
                uint32_t ah[4], al[4];
                ldsm4(ah[0], ah[1], ah[2], ah[3], ag + ks * 32);
                ldsm4(al[0], al[1], al[2], al[3], ag + 104448 + ks * 32);
                mma16816(C[g], ah, bhf[ks][0], bhf[ks][1]);
                mma16816(C[g], ah, blf[ks][0], blf[ks][1]);
                mma16816(C[g], al, bhf[ks][0], bhf[ks][1]);
            }
        }

        // gates
        float hnew[4];
        #pragma unroll
        for (int q = 0; q < 4; q++) {
            int js = (q >> 1);
            float r = sigm_fast(C[0][q] + br[js] + giv[0][q]);
            float z = sigm_fast(C[1][q] + bz[js] + giv[1][q]);
            float n = tanhf_fast(giv[2][q] + r * (C[2][q] + bn[js]));
            hnew[q] = n + z * (hprev[q] - n);
            hprev[q] = hnew[q];
        }

        __syncthreads();   // all B-frag reads of h done

        // publish new h as bf16 hi/lo at [k=j][b]
        #pragma unroll
        for (int q = 0; q < 4; q++) {
            int j = (q & 2) ? j1 : j0;
            int c = c0 + (q & 1);
            __nv_bfloat16 h, l;
            split_bf16(hnew[q], h, l);
            *(__nv_bfloat16*)(smem + SH_HI + j * 16 + c * 2) = h;
            *(__nv_bfloat16*)(smem + SH_LO + j * 16 + c * 2) = l;
        }
    }

    if (valid) {
        #pragma unroll
        for (int q = 0; q < 4; q++) {
            int j = (q & 2) ? j1 : j0;
            int c = c0 + (q & 1);
            out[(r0 + c) * DIM + j] = hprev[q];
        }
    }
}

// ---------------- launch ----------------
extern "C" void kernel_launch(void* const* d_in, const int* in_sizes, int n_in,
                              void* d_out, int out_size) {
    const float* x    = (const float*)d_in[0];
    const float* W1   = (const float*)d_in[1];
    const float* b1   = (const float*)d_in[2];
    const float* W_ih = (const float*)d_in[3];
    const float* W_hh = (const float*)d_in[4];
    const float* b_ih = (const float*)d_in[5];
    const float* b_hh = (const float*)d_in[6];
    float* out = (float*)d_out;

    static bool attr_done = false;
    if (!attr_done) {
        cudaFuncSetAttribute(gi_gemm_hmma,
                             cudaFuncAttributeMaxDynamicSharedMemorySize, GSMEM);
        cudaFuncSetAttribute(gru_scan_hmma,
                             cudaFuncAttributeMaxDynamicSharedMemorySize, S2SMEM);
        attr_done = true;
    }

    prep_kernel<<<GATES, DIM>>>(W1, b1, W_ih, b_ih);
    gi_gemm_hmma<<<dim3(3, 8192), 256, GSMEM>>>(x);
    gru_scan_hmma<<<128, 256, S2SMEM>>>(W_hh, b_hh, out);
}